// round 15
// baseline (speedup 1.0000x reference)
#include <cuda_runtime.h>
#include <cuda_bf16.h>
#include <math.h>
#include <stdint.h>

// Problem constants
#define B_ 128
#define T_ 256
#define E_ 384
#define H_ 6
#define HS_ 64
#define L_ 6
#define V_ 78
#define FF_ 1536
#define QKV3_ 192
#define NQKV_ (H_ * QKV3_)  // 1152
#define BT_ (B_ * T_)       // 32768
#define VPAD_ 128

__device__ __forceinline__ uint32_t f2tf32(float f) {
    uint32_t r;
    asm("cvt.rna.tf32.f32 %0, %1;" : "=r"(r) : "f"(f));
    return r;
}
__device__ __forceinline__ float roundtf(float f) { return __uint_as_float(f2tf32(f)); }

// ldmatrix.x4 fragment load from row-major smem (stride in words, 16B-aligned rows).
// d0=(row0+gid, col0+tig), d1=(row0+8+gid, col0+tig),
// d2=(row0+gid, col0+4+tig), d3=(row0+8+gid, col0+4+tig)  [b32 view]
__device__ __forceinline__ void ldsm_x4(uint32_t& d0, uint32_t& d1, uint32_t& d2, uint32_t& d3,
                                        const float* smem, int row0, int col0, int stride) {
    int lane = threadIdx.x & 31;
    int m = lane >> 3, r = lane & 7;
    const float* addr = smem + (size_t)(row0 + r + (m & 1) * 8) * stride + col0 + (m >> 1) * 4;
    uint32_t saddr = (uint32_t)__cvta_generic_to_shared(addr);
    asm volatile("ldmatrix.sync.aligned.m8n8.x4.shared.b16 {%0,%1,%2,%3}, [%4];"
                 : "=r"(d0), "=r"(d1), "=r"(d2), "=r"(d3) : "r"(saddr));
}

// ---------------- device scratch ----------------
// All weight copies stored TRANSPOSED: [N][K], tf32-rounded.
__device__ float g_x   [BT_ * E_];
__device__ float g_xn  [BT_ * E_];
__device__ float g_qkv [BT_ * NQKV_];
__device__ float g_obuf[BT_ * E_];
__device__ float g_ff  [BT_ * FF_];
__device__ float g_wq  [L_ * NQKV_ * E_];   // [L][1152][384]
__device__ float g_wp  [L_ * E_ * E_];      // [L][384][384] (transposed)
__device__ float g_w1r [L_ * FF_ * E_];     // [L][1536][384]
__device__ float g_w2r [L_ * E_ * FF_];     // [L][384][1536]
__device__ float g_whr [VPAD_ * E_];        // [128][384]
__device__ float g_bhr [VPAD_];

// ---------------- fused prep (all weights written transposed) ----------------
#define NE_ (BT_ * E_)
#define NQ_ (L_ * NQKV_ * E_)
#define NP_ (L_ * E_ * E_)
#define N1_ (L_ * FF_ * E_)
#define N2_ (L_ * E_ * FF_)
#define NH_ (VPAD_ * E_)
#define NTOT_ (NE_ + NQ_ + NP_ + N1_ + N2_ + NH_ + VPAD_)

__global__ void prep_all_kernel(const int* __restrict__ ctx,
                                const float* __restrict__ tok,
                                const float* __restrict__ pos,
                                const float* __restrict__ wqkv,    // [L][H][E][192]
                                const float* __restrict__ wproj,   // [L][E][E]
                                const float* __restrict__ w1,      // [L][E][FF]
                                const float* __restrict__ w2,      // [L][FF][E]
                                const float* __restrict__ whead,   // [E][V]
                                const float* __restrict__ bhead,
                                float* __restrict__ x,
                                float* __restrict__ wq,
                                float* __restrict__ wp,
                                float* __restrict__ w1r,
                                float* __restrict__ w2r,
                                float* __restrict__ whr,
                                float* __restrict__ bhr) {
    int i = blockIdx.x * blockDim.x + threadIdx.x;
    if (i < NE_) {
        int e  = i % E_;
        int bt = i / E_;
        int t  = bt % T_;
        x[i] = tok[ctx[bt] * E_ + e] + pos[t * E_ + e];
        return;
    }
    i -= NE_;
    if (i < NQ_) {   // dst [L][NQKV][E]; src [L][H][E][192]
        int e = i % E_;
        int n = (i / E_) % NQKV_;
        int l = i / (E_ * NQKV_);
        int h = n / QKV3_, f = n % QKV3_;
        wq[i] = roundtf(wqkv[(((size_t)l * H_ + h) * E_ + e) * QKV3_ + f]);
        return;
    }
    i -= NQ_;
    if (i < NP_) {   // dst [L][N=E][K=E]; src [L][K][N]
        int k = i % E_;
        int n = (i / E_) % E_;
        int l = i / (E_ * E_);
        wp[i] = roundtf(wproj[((size_t)l * E_ + k) * E_ + n]);
        return;
    }
    i -= NP_;
    if (i < N1_) {   // dst [L][N=FF][K=E]; src [L][E][FF]
        int k = i % E_;
        int n = (i / E_) % FF_;
        int l = i / (E_ * FF_);
        w1r[i] = roundtf(w1[((size_t)l * E_ + k) * FF_ + n]);
        return;
    }
    i -= N1_;
    if (i < N2_) {   // dst [L][N=E][K=FF]; src [L][FF][E]
        int k = i % FF_;
        int n = (i / FF_) % E_;
        int l = i / (FF_ * E_);
        w2r[i] = roundtf(w2[((size_t)l * FF_ + k) * E_ + n]);
        return;
    }
    i -= N2_;
    if (i < NH_) {   // dst [VPAD][E]; src [E][V]
        int k = i % E_;
        int n = i / E_;
        whr[i] = (n < V_) ? roundtf(whead[(size_t)k * V_ + n]) : 0.f;
        return;
    }
    i -= NH_;
    if (i < VPAD_) bhr[i] = (i < V_) ? bhead[i] : 0.f;
}

// ---------------- layernorm ----------------
__global__ __launch_bounds__(256)
void ln_kernel(const float* __restrict__ x,
               const float* __restrict__ g,
               const float* __restrict__ bta,
               float* __restrict__ y) {
    const int warp = threadIdx.x >> 5, lane = threadIdx.x & 31;
    const int row  = blockIdx.x * 8 + warp;
    const float4* xp = (const float4*)(x + (size_t)row * E_);
    const float4* gp = (const float4*)g;
    const float4* bp = (const float4*)bta;
    float4* yp = (float4*)(y + (size_t)row * E_);

    float4 v[3];
    float s = 0.f, sq = 0.f;
#pragma unroll
    for (int i = 0; i < 3; i++) {
        v[i] = xp[lane + i * 32];
        s  += v[i].x + v[i].y + v[i].z + v[i].w;
        sq += v[i].x * v[i].x + v[i].y * v[i].y + v[i].z * v[i].z + v[i].w * v[i].w;
    }
#pragma unroll
    for (int off = 16; off; off >>= 1) {
        s  += __shfl_xor_sync(0xffffffffu, s,  off);
        sq += __shfl_xor_sync(0xffffffffu, sq, off);
    }
    const float invE = 1.0f / E_;
    float mu  = s * invE;
    float var = sq * invE - mu * mu;
    float inv = rsqrtf(var + 1e-5f);
#pragma unroll
    for (int i = 0; i < 3; i++) {
        float4 gv = gp[lane + i * 32];
        float4 bv = bp[lane + i * 32];
        float4 ov;
        ov.x = roundtf((v[i].x - mu) * inv * gv.x + bv.x);
        ov.y = roundtf((v[i].y - mu) * inv * gv.y + bv.y);
        ov.z = roundtf((v[i].z - mu) * inv * gv.z + bv.z);
        ov.w = roundtf((v[i].w - mu) * inv * gv.w + bv.w);
        yp[lane + i * 32] = ov;
    }
}

// ---------------- cp.async helpers ----------------
__device__ __forceinline__ void cp_async16(float* smem_ptr, const float* gptr) {
    uint32_t saddr = (uint32_t)__cvta_generic_to_shared(smem_ptr);
    asm volatile("cp.async.cg.shared.global [%0], [%1], 16;" :: "r"(saddr), "l"(gptr));
}
#define CP_COMMIT() asm volatile("cp.async.commit_group;")
#define CP_WAIT0()  asm volatile("cp.async.wait_group 0;")

// ---------------- TF32 GEMM: both operands ldmatrix, B pre-transposed [N][K] ----------------
// 128x128 CTA tile, 8 warps (2m x 4n), warp 64x32, mma m16n8k8.
// A: [M][K] activations. Bt: [N][K] transposed weights. M%128==0, N%128==0, K%32==0.
#define TS_STRIDE 36
#define TILE_ELEMS (128 * TS_STRIDE)
#define GEMM_SMEM_BYTES (4 * TILE_ELEMS * 4)   // 73728

template <bool RELU, bool RESID, bool BIAS, bool ROUND_OUT, bool NGUARD>
__global__ __launch_bounds__(256, 2)
void gemm_tf32(const float* __restrict__ A, const float* __restrict__ Bt,
               const float* __restrict__ bias, const float* __restrict__ resid,
               float* __restrict__ C, int M, int N, int K, int ldc, int n_out) {
    extern __shared__ float sm[];
    float* Asm = sm;                      // [2][128][36]
    float* Bsm = sm + 2 * TILE_ELEMS;     // [2][128][36]

    const int tid  = threadIdx.x;
    const int wid  = tid >> 5, lane = tid & 31;
    const int gid  = lane >> 2, tig = lane & 3;
    const int wm   = wid & 1;
    const int wn   = wid >> 1;
    const int bm   = blockIdx.y * 128;
    const int bn   = blockIdx.x * 128;

    const int cr[4] = { (tid + 0) >> 3, (tid + 256) >> 3, (tid + 512) >> 3, (tid + 768) >> 3 };
    const int ccol  = (tid & 7) * 4;

    float c[4][4][4] = {};
    const int ntiles = K >> 5;

    {
#pragma unroll
        for (int u = 0; u < 4; u++) {
            cp_async16(Asm + cr[u] * TS_STRIDE + ccol, A + (size_t)(bm + cr[u]) * K + ccol);
            cp_async16(Bsm + cr[u] * TS_STRIDE + ccol, Bt + (size_t)(bn + cr[u]) * K + ccol);
        }
        CP_COMMIT();
    }

    for (int t = 0; t < ntiles; t++) {
        CP_WAIT0();
        __syncthreads();

        if (t + 1 < ntiles) {
            const int k0 = (t + 1) << 5;
            float* An = Asm + ((t + 1) & 1) * TILE_ELEMS;
            float* Bn = Bsm + ((t + 1) & 1) * TILE_ELEMS;
#pragma unroll
            for (int u = 0; u < 4; u++) {
                cp_async16(An + cr[u] * TS_STRIDE + ccol, A + (size_t)(bm + cr[u]) * K + k0 + ccol);
                cp_async16(Bn + cr[u] * TS_STRIDE + ccol, Bt + (size_t)(bn + cr[u]) * K + k0 + ccol);
            }
            CP_COMMIT();
        }

        const float* Ab = Asm + (t & 1) * TILE_ELEMS;
        const float* Bb = Bsm + (t & 1) * TILE_ELEMS;
#pragma unroll
        for (int kk = 0; kk < 4; kk++) {
            const int kb = kk * 8;
            uint32_t af[4][4], bf[4][2];
#pragma unroll
            for (int mt = 0; mt < 4; mt++)
                ldsm_x4(af[mt][0], af[mt][1], af[mt][2], af[mt][3],
                        Ab, wm * 64 + mt * 16, kb, TS_STRIDE);
#pragma unroll
            for (int p = 0; p < 2; p++) {
                uint32_t d0, d1, d2, d3;
                ldsm_x4(d0, d1, d2, d3, Bb, wn * 32 + p * 16, kb, TS_STRIDE);
                bf[2 * p][0] = d0; bf[2 * p + 1][0] = d1;
                bf[2 * p][1] = d2; bf[2 * p + 1][1] = d3;
            }
#pragma unroll
            for (int mt = 0; mt < 4; mt++)
#pragma unroll
                for (int nt = 0; nt < 4; nt++)
                    asm volatile(
                        "mma.sync.aligned.m16n8k8.row.col.f32.tf32.tf32.f32 "
                        "{%0,%1,%2,%3},{%4,%5,%6,%7},{%8,%9},{%0,%1,%2,%3};"
                        : "+f"(c[mt][nt][0]), "+f"(c[mt][nt][1]),
                          "+f"(c[mt][nt][2]), "+f"(c[mt][nt][3])
                        : "r"(af[mt][0]), "r"(af[mt][1]), "r"(af[mt][2]), "r"(af[mt][3]),
                          "r"(bf[nt][0]), "r"(bf[nt][1]));
        }
    }

#pragma unroll
    for (int mt = 0; mt < 4; mt++) {
        int r0 = bm + wm * 64 + mt * 16 + gid;
#pragma unroll
        for (int nt = 0; nt < 4; nt++) {
            int cn = bn + wn * 32 + nt * 8 + tig * 2;
            if (NGUARD && cn >= n_out) continue;
            float v0 = c[mt][nt][0], v1 = c[mt][nt][1];
            float v2 = c[mt][nt][2], v3 = c[mt][nt][3];
            if (BIAS) {
                float b0 = bias[cn], b1 = bias[cn + 1];
                v0 += b0; v1 += b1; v2 += b0; v3 += b1;
            }
            if (RELU) {
                v0 = fmaxf(v0, 0.f); v1 = fmaxf(v1, 0.f);
                v2 = fmaxf(v2, 0.f); v3 = fmaxf(v3, 0.f);
            }
            if (RESID) {
                const float2 ra = *(const float2*)(resid + (size_t)r0 * ldc + cn);
                const float2 rb = *(const float2*)(resid + (size_t)(r0 + 8) * ldc + cn);
                v0 += ra.x; v1 += ra.y; v2 += rb.x; v3 += rb.y;
            }
            if (ROUND_OUT) {
                v0 = roundtf(v0); v1 = roundtf(v1);
                v2 = roundtf(v2); v3 = roundtf(v3);
            }
            *(float2*)(C + (size_t)r0 * ldc + cn)       = make_float2(v0, v1);
            *(float2*)(C + (size_t)(r0 + 8) * ldc + cn) = make_float2(v2, v3);
        }
    }
}

// ---------------- TF32 mma flash attention (unchanged from R14) ----------------
#define QS_STR 68
#define KS_STR 68
#define VS_STR 72
#define SS_STR 68
#define FA_SMEM_FLOATS (64*QS_STR + 64*KS_STR + 64*VS_STR + 64*SS_STR + 256 + 256 + 64*3)

__global__ __launch_bounds__(256)
void flash_attn(const float* __restrict__ qkv, float* __restrict__ o) {
    extern __shared__ float sm[];
    float* Qs      = sm;
    float* Ks      = Qs + 64 * QS_STR;
    float* Vs      = Ks + 64 * KS_STR;
    float* Ss      = Vs + 64 * VS_STR;
    float* part_m  = Ss + 64 * SS_STR;
    float* part_s  = part_m + 256;
    float* m_s     = part_s + 256;
    float* l_s     = m_s + 64;
    float* alpha_s = l_s + 64;

    const int qt = blockIdx.x;
    const int h  = blockIdx.y;
    const int b  = blockIdx.z;
    const int tid = threadIdx.x;
    const int wid = tid >> 5, lane = tid & 31;
    const int gid = lane >> 2, tig = lane & 3;
    const int wm  = wid & 3;
    const int wn  = wid >> 2;

    const float* base = qkv + (size_t)b * T_ * NQKV_ + h * QKV3_;

    const int cr = tid >> 4;
    const int cc = (tid & 15) * 4;

#pragma unroll
    for (int u = 0; u < 4; u++) {
        int r = cr + u * 16;
        cp_async16(Qs + r * QS_STR + cc, base + (size_t)(qt * 64 + r) * NQKV_ + cc);
    }
    CP_COMMIT();
    if (tid < 64) { m_s[tid] = -1e30f; l_s[tid] = 0.f; }

    float oacc[4][4] = {};
    const int r0 = wm * 16 + gid;

    for (int kt = 0; kt <= qt; kt++) {
#pragma unroll
        for (int u = 0; u < 4; u++) {
            int r = cr + u * 16;
            const float* rowp = base + (size_t)(kt * 64 + r) * NQKV_;
            cp_async16(Ks + r * KS_STR + cc, rowp + HS_ + cc);
            cp_async16(Vs + r * VS_STR + cc, rowp + 2 * HS_ + cc);
        }
        CP_COMMIT();
        CP_WAIT0();
        __syncthreads();

        float sc[4][4] = {};
#pragma unroll
        for (int kk = 0; kk < 8; kk++) {
            const int kb = kk * 8;
            uint32_t af[4], bf[4][2];
            ldsm_x4(af[0], af[1], af[2], af[3], Qs, wm * 16, kb, QS_STR);
#pragma unroll
            for (int p = 0; p < 2; p++) {
                uint32_t d0, d1, d2, d3;
                ldsm_x4(d0, d1, d2, d3, Ks, wn * 32 + p * 16, kb, KS_STR);
                bf[2 * p][0] = d0; bf[2 * p + 1][0] = d1;
                bf[2 * p][1] = d2; bf[2 * p + 1][1] = d3;
            }
#pragma unroll
            for (int nt = 0; nt < 4; nt++)
                asm volatile(
                    "mma.sync.aligned.m16n8k8.row.col.f32.tf32.tf32.f32 "
                    "{%0,%1,%2,%3},{%4,%5,%6,%7},{%8,%9},{%0,%1,%2,%3};"
                    : "+f"(sc[nt][0]), "+f"(sc[nt][1]), "+f"(sc[nt][2]), "+f"(sc[nt][3])
                    : "r"(af[0]), "r"(af[1]), "r"(af[2]), "r"(af[3]),
                      "r"(bf[nt][0]), "r"(bf[nt][1]));
        }

        const bool diag = (kt == qt);
#pragma unroll
        for (int nt = 0; nt < 4; nt++) {
            int gj = wn * 32 + nt * 8 + tig * 2;
            float v0 = sc[nt][0] * 0.125f;
            float v1 = sc[nt][1] * 0.125f;
            float v2 = sc[nt][2] * 0.125f;
            float v3 = sc[nt][3] * 0.125f;
            if (diag) {
                if (gj     > r0    ) v0 = -1e30f;
                if (gj + 1 > r0    ) v1 = -1e30f;
                if (gj     > r0 + 8) v2 = -1e30f;
                if (gj + 1 > r0 + 8) v3 = -1e30f;
            }
            *(float2*)&Ss[(r0    ) * SS_STR + gj] = make_float2(v0, v1);
            *(float2*)&Ss[(r0 + 8) * SS_STR + gj] = make_float2(v2, v3);
        }
        __syncthreads();

        {
            int row = tid >> 2, seg = tid & 3, cb = seg * 16;
            float4 vv[4];
#pragma unroll
            for (int i = 0; i < 4; i++) vv[i] = *(float4*)&Ss[row * SS_STR + cb + i * 4];
            float mx = -1e30f;
#pragma unroll
            for (int i = 0; i < 4; i++)
                mx = fmaxf(mx, fmaxf(fmaxf(vv[i].x, vv[i].y), fmaxf(vv[i].z, vv[i].w)));
            part_m[tid] = mx;
            __syncwarp();
            float m_old = m_s[row];
            float m_new = fmaxf(fmaxf(part_m[row * 4 + 0], part_m[row * 4 + 1]),
                                fmaxf(part_m[row * 4 + 2], part_m[row * 4 + 3]));
            m_new = fmaxf(m_old, m_new);
            float ps = 0.f;
#pragma unroll
            for (int i = 0; i < 4; i++) {
                float4 pv;
                pv.x = roundtf(__expf(vv[i].x - m_new));
                pv.y = roundtf(__expf(vv[i].y - m_new));
                pv.z = roundtf(__expf(vv[i].z - m_new));
                pv.w = roundtf(__expf(vv[i].w - m_new));
                ps += pv.x; ps += pv.y; ps += pv.z; ps += pv.w;
                *(float4*)&Ss[row * SS_STR + cb + i * 4] = pv;
            }
            part_s[tid] = ps;
            __syncwarp();
            if (seg == 0) {
                float alpha = __expf(m_old - m_new);
                alpha_s[row] = alpha;
                m_s[row] = m_new;
                l_s[row] = l_s[row] * alpha +
                           part_s[row * 4 + 0] + part_s[row * 4 + 1] +
                           part_s[row * 4 + 2] + part_s[row * 4 + 3];
            }
        }
        __syncthreads();

        {
            float a0 = alpha_s[r0], a1 = alpha_s[r0 + 8];
#pragma unroll
            for (int nt = 0; nt < 4; nt++) {
                oacc[nt][0] *= a0; oacc[nt][1] *= a0;
                oacc[nt][2] *= a1; oacc[nt][3] *= a1;
            }
#pragma unroll
            for (int kk = 0; kk < 8; kk++) {
                const int kb = kk * 8;
                uint32_t af[4], bf[4][2];
                ldsm_x4(af[0], af[1], af[2], af[3], Ss, wm * 16, kb, SS_STR);
#pragma unroll
                for (int nt = 0; nt < 4; nt++) {
                    int cn = wn * 32 + nt * 8 + gid;
                    bf[nt][0] = __float_as_uint(Vs[(kb + tig    ) * VS_STR + cn]);
                    bf[nt][1] = __float_as_uint(Vs[(kb + tig + 4) * VS_STR + cn]);
                }
#pragma unroll
                for (int nt = 0; nt < 4; nt++)
                    asm volatile(
                        "mma.sync.aligned.m16n8k8.row.col.f32.tf32.tf32.f32 "
                        "{%0,%1,%2,%3},{%4,%5,%6,%7},{%8,%9},{%0,%1,%2,%3};"
                        : "+f"(oacc[nt][0]), "+f"(oacc[nt][1]), "+f"(oacc[nt][2]), "+f"(oacc[nt][3])
                        : "r"(af[0]), "r"(af[1]), "r"(af[2]), "r"(af[3]),
                          "r"(bf[nt][0]), "r"(bf[nt][1]));
            }
        }
        __syncthreads();
    }

    {
        float invl0 = 1.0f / l_s[r0];
        float invl1 = 1.0f / l_s[r0 + 8];
        int t0 = qt * 64 + r0;
#pragma unroll
        for (int nt = 0; nt < 4; nt++) {
            int cn = wn * 32 + nt * 8 + tig * 2;
            float* p0 = o + (size_t)(b * T_ + t0) * E_ + h * HS_ + cn;
            float* p1 = o + (size_t)(b * T_ + t0 + 8) * E_ + h * HS_ + cn;
            *(float2*)p0 = make_float2(roundtf(oacc[nt][0] * invl0), roundtf(oacc[nt][1] * invl0));
            *(float2*)p1 = make_float2(roundtf(oacc[nt][2] * invl1), roundtf(oacc[nt][3] * invl1));
        }
    }
}

// ---------------- host orchestration ----------------
extern "C" void kernel_launch(void* const* d_in, const int* in_sizes, int n_in,
                              void* d_out, int out_size) {
    const int*   context = (const int*)  d_in[0];
    const float* tok_emb = (const float*)d_in[1];
    const float* pos_emb = (const float*)d_in[2];
    const float* ln1_g   = (const float*)d_in[3];
    const float* ln1_b   = (const float*)d_in[4];
    const float* w_qkv   = (const float*)d_in[5];
    const float* w_proj  = (const float*)d_in[6];
    const float* b_proj  = (const float*)d_in[7];
    const float* ln2_g   = (const float*)d_in[8];
    const float* ln2_b   = (const float*)d_in[9];
    const float* w1      = (const float*)d_in[10];
    const float* b1      = (const float*)d_in[11];
    const float* w2      = (const float*)d_in[12];
    const float* b2      = (const float*)d_in[13];
    const float* lnf_g   = (const float*)d_in[14];
    const float* lnf_b   = (const float*)d_in[15];
    const float* w_head  = (const float*)d_in[16];
    const float* b_head  = (const float*)d_in[17];
    float* out = (float*)d_out;

    float *x, *xn, *qkv, *obuf, *ff, *wq, *wp, *w1r, *w2r, *whr, *bhr;
    cudaGetSymbolAddress((void**)&x,    g_x);
    cudaGetSymbolAddress((void**)&xn,   g_xn);
    cudaGetSymbolAddress((void**)&qkv,  g_qkv);
    cudaGetSymbolAddress((void**)&obuf, g_obuf);
    cudaGetSymbolAddress((void**)&ff,   g_ff);
    cudaGetSymbolAddress((void**)&wq,   g_wq);
    cudaGetSymbolAddress((void**)&wp,   g_wp);
    cudaGetSymbolAddress((void**)&w1r,  g_w1r);
    cudaGetSymbolAddress((void**)&w2r,  g_w2r);
    cudaGetSymbolAddress((void**)&whr,  g_whr);
    cudaGetSymbolAddress((void**)&bhr,  g_bhr);

    static bool attr_done = false;
    if (!attr_done) {
        cudaFuncSetAttribute(flash_attn, cudaFuncAttributeMaxDynamicSharedMemorySize,
                             FA_SMEM_FLOATS * 4);
        cudaFuncSetAttribute(gemm_tf32<false, false, false, true, false>,
                             cudaFuncAttributeMaxDynamicSharedMemorySize, GEMM_SMEM_BYTES);
        cudaFuncSetAttribute(gemm_tf32<false, true, true, false, false>,
                             cudaFuncAttributeMaxDynamicSharedMemorySize, GEMM_SMEM_BYTES);
        cudaFuncSetAttribute(gemm_tf32<true, false, true, true, false>,
                             cudaFuncAttributeMaxDynamicSharedMemorySize, GEMM_SMEM_BYTES);
        cudaFuncSetAttribute(gemm_tf32<false, false, true, false, true>,
                             cudaFuncAttributeMaxDynamicSharedMemorySize, GEMM_SMEM_BYTES);
        attr_done = true;
    }

    prep_all_kernel<<<(NTOT_ + 255) / 256, 256>>>(
        context, tok_emb, pos_emb, w_qkv, w_proj, w1, w2, w_head, b_head,
        x, wq, wp, w1r, w2r, whr, bhr);

    for (int l = 0; l < L_; l++) {
        ln_kernel<<<BT_ / 8, 256>>>(x, ln1_g + l * E_, ln1_b + l * E_, xn);
        {
            dim3 grid(NQKV_ / 128, BT_ / 128);
            gemm_tf32<false, false, false, true, false><<<grid, 256, GEMM_SMEM_BYTES>>>(
                xn, wq + (size_t)l * NQKV_ * E_, nullptr, nullptr, qkv,
                BT_, NQKV_, E_, NQKV_, NQKV_);
        }
        {
            dim3 grid(T_ / 64, H_, B_);
            flash_attn<<<grid, 256, FA_SMEM_FLOATS * 4>>>(qkv, obuf);
        }
        {
            dim3 grid(E_ / 128, BT_ / 128);
            gemm_tf32<false, true, true, false, false><<<grid, 256, GEMM_SMEM_BYTES>>>(
                obuf, wp + (size_t)l * E_ * E_, b_proj + l * E_, x, x,
                BT_, E_, E_, E_, E_);
        }
        ln_kernel<<<BT_ / 8, 256>>>(x, ln2_g + l * E_, ln2_b + l * E_, xn);
        {
            dim3 grid(FF_ / 128, BT_ / 128);
            gemm_tf32<true, false, true, true, false><<<grid, 256, GEMM_SMEM_BYTES>>>(
                xn, w1r + (size_t)l * FF_ * E_, b1 + l * FF_, nullptr, ff,
                BT_, FF_, E_, FF_, FF_);
        }
        {
            dim3 grid(E_ / 128, BT_ / 128);
            gemm_tf32<false, true, true, false, false><<<grid, 256, GEMM_SMEM_BYTES>>>(
                ff, w2r + (size_t)l * E_ * FF_, b2 + l * E_, x, x,
                BT_, E_, FF_, E_, E_);
        }
    }
    ln_kernel<<<BT_ / 8, 256>>>(x, lnf_g, lnf_b, xn);
    {
        dim3 grid(VPAD_ / 128, BT_ / 128);
        gemm_tf32<false, false, true, false, true><<<grid, 256, GEMM_SMEM_BYTES>>>(
            xn, whr, bhr, nullptr, out, BT_, VPAD_, E_, V_, V_);
    }
}

// round 16
// speedup vs baseline: 1.1183x; 1.1183x over previous
#include <cuda_runtime.h>
#include <cuda_bf16.h>
#include <math.h>
#include <stdint.h>

// Problem constants
#define B_ 128
#define T_ 256
#define E_ 384
#define H_ 6
#define HS_ 64
#define L_ 6
#define V_ 78
#define FF_ 1536
#define QKV3_ 192
#define NQKV_ (H_ * QKV3_)  // 1152
#define BT_ (B_ * T_)       // 32768
#define VPAD_ 128

__device__ __forceinline__ uint32_t f2tf32(float f) {
    uint32_t r;
    asm("cvt.rna.tf32.f32 %0, %1;" : "=r"(r) : "f"(f));
    return r;
}
__device__ __forceinline__ float roundtf(float f) { return __uint_as_float(f2tf32(f)); }

// ldmatrix.x4 fragment load from row-major smem (stride in words, 16B-aligned rows).
__device__ __forceinline__ void ldsm_x4(uint32_t& d0, uint32_t& d1, uint32_t& d2, uint32_t& d3,
                                        const float* smem, int row0, int col0, int stride) {
    int lane = threadIdx.x & 31;
    int m = lane >> 3, r = lane & 7;
    const float* addr = smem + (size_t)(row0 + r + (m & 1) * 8) * stride + col0 + (m >> 1) * 4;
    uint32_t saddr = (uint32_t)__cvta_generic_to_shared(addr);
    asm volatile("ldmatrix.sync.aligned.m8n8.x4.shared.b16 {%0,%1,%2,%3}, [%4];"
                 : "=r"(d0), "=r"(d1), "=r"(d2), "=r"(d3) : "r"(saddr));
}

// ---------------- device scratch (R14 layouts: weights k-major) ----------------
__device__ float g_x   [BT_ * E_];
__device__ float g_xn  [BT_ * E_];
__device__ float g_qkv [BT_ * NQKV_];
__device__ float g_obuf[BT_ * E_];
__device__ float g_ff  [BT_ * FF_];
__device__ float g_wq  [L_ * E_ * NQKV_];
__device__ float g_wp  [L_ * E_ * E_];
__device__ float g_w1r [L_ * E_ * FF_];
__device__ float g_w2r [L_ * FF_ * E_];
__device__ float g_whr [E_ * VPAD_];
__device__ float g_bhr [VPAD_];

// ---------------- fused prep ----------------
#define NE_ (BT_ * E_)
#define NQ_ (L_ * H_ * E_ * QKV3_)
#define NP_ (L_ * E_ * E_)
#define N1_ (L_ * E_ * FF_)
#define N2_ (L_ * FF_ * E_)
#define NH_ (E_ * VPAD_)
#define NTOT_ (NE_ + NQ_ + NP_ + N1_ + N2_ + NH_ + VPAD_)

__global__ void prep_all_kernel(const int* __restrict__ ctx,
                                const float* __restrict__ tok,
                                const float* __restrict__ pos,
                                const float* __restrict__ wqkv,
                                const float* __restrict__ wproj,
                                const float* __restrict__ w1,
                                const float* __restrict__ w2,
                                const float* __restrict__ whead,
                                const float* __restrict__ bhead,
                                float* __restrict__ x,
                                float* __restrict__ wq,
                                float* __restrict__ wp,
                                float* __restrict__ w1r,
                                float* __restrict__ w2r,
                                float* __restrict__ whr,
                                float* __restrict__ bhr) {
    int i = blockIdx.x * blockDim.x + threadIdx.x;
    if (i < NE_) {
        int e  = i % E_;
        int bt = i / E_;
        int t  = bt % T_;
        x[i] = tok[ctx[bt] * E_ + e] + pos[t * E_ + e];
        return;
    }
    i -= NE_;
    if (i < NQ_) {
        int f = i % QKV3_;
        int e = (i / QKV3_) % E_;
        int h = (i / (QKV3_ * E_)) % H_;
        int l = i / (QKV3_ * E_ * H_);
        wq[((size_t)l * E_ + e) * NQKV_ + h * QKV3_ + f] = roundtf(wqkv[i]);
        return;
    }
    i -= NQ_;
    if (i < NP_) { wp[i] = roundtf(wproj[i]); return; }
    i -= NP_;
    if (i < N1_) { w1r[i] = roundtf(w1[i]); return; }
    i -= N1_;
    if (i < N2_) { w2r[i] = roundtf(w2[i]); return; }
    i -= N2_;
    if (i < NH_) {
        int col = i % VPAD_, row = i / VPAD_;
        whr[i] = (col < V_) ? roundtf(whead[row * V_ + col]) : 0.f;
        return;
    }
    i -= NH_;
    if (i < VPAD_) bhr[i] = (i < V_) ? bhead[i] : 0.f;
}

// ---------------- layernorm ----------------
__global__ __launch_bounds__(256)
void ln_kernel(const float* __restrict__ x,
               const float* __restrict__ g,
               const float* __restrict__ bta,
               float* __restrict__ y) {
    const int warp = threadIdx.x >> 5, lane = threadIdx.x & 31;
    const int row  = blockIdx.x * 8 + warp;
    const float4* xp = (const float4*)(x + (size_t)row * E_);
    const float4* gp = (const float4*)g;
    const float4* bp = (const float4*)bta;
    float4* yp = (float4*)(y + (size_t)row * E_);

    float4 v[3];
    float s = 0.f, sq = 0.f;
#pragma unroll
    for (int i = 0; i < 3; i++) {
        v[i] = xp[lane + i * 32];
        s  += v[i].x + v[i].y + v[i].z + v[i].w;
        sq += v[i].x * v[i].x + v[i].y * v[i].y + v[i].z * v[i].z + v[i].w * v[i].w;
    }
#pragma unroll
    for (int off = 16; off; off >>= 1) {
        s  += __shfl_xor_sync(0xffffffffu, s,  off);
        sq += __shfl_xor_sync(0xffffffffu, sq, off);
    }
    const float invE = 1.0f / E_;
    float mu  = s * invE;
    float var = sq * invE - mu * mu;
    float inv = rsqrtf(var + 1e-5f);
#pragma unroll
    for (int i = 0; i < 3; i++) {
        float4 gv = gp[lane + i * 32];
        float4 bv = bp[lane + i * 32];
        float4 ov;
        ov.x = roundtf((v[i].x - mu) * inv * gv.x + bv.x);
        ov.y = roundtf((v[i].y - mu) * inv * gv.y + bv.y);
        ov.z = roundtf((v[i].z - mu) * inv * gv.z + bv.z);
        ov.w = roundtf((v[i].w - mu) * inv * gv.w + bv.w);
        yp[lane + i * 32] = ov;
    }
}

// ---------------- cp.async helpers ----------------
__device__ __forceinline__ void cp_async16(float* smem_ptr, const float* gptr) {
    uint32_t saddr = (uint32_t)__cvta_generic_to_shared(smem_ptr);
    asm volatile("cp.async.cg.shared.global [%0], [%1], 16;" :: "r"(saddr), "l"(gptr));
}
#define CP_COMMIT() asm volatile("cp.async.commit_group;")
#define CP_WAIT0()  asm volatile("cp.async.wait_group 0;")
#define CP_WAIT1()  asm volatile("cp.async.wait_group 1;")

// ---------------- TF32 GEMM (R14: 2-stage cp.async + ldmatrix A-fragments) ----------------
#define AS_STRIDE 36
#define BS_STRIDE 136
#define AS_ELEMS (128 * AS_STRIDE)
#define BS_ELEMS (32 * BS_STRIDE)
#define GEMM_SMEM_BYTES ((2 * AS_ELEMS + 2 * BS_ELEMS) * 4)   // 71680

template <bool RELU, bool RESID, bool BIAS, bool ROUND_OUT, bool NGUARD>
__global__ __launch_bounds__(256, 2)
void gemm_tf32(const float* __restrict__ A, const float* __restrict__ Bm,
               const float* __restrict__ bias, const float* __restrict__ resid,
               float* __restrict__ C, int M, int N, int K, int ldc, int n_out) {
    extern __shared__ float sm[];
    float* Asm = sm;
    float* Bsm = sm + 2 * AS_ELEMS;

    const int tid  = threadIdx.x;
    const int wid  = tid >> 5, lane = tid & 31;
    const int gid  = lane >> 2, tig = lane & 3;
    const int wm   = wid & 1;
    const int wn   = wid >> 1;
    const int bm   = blockIdx.y * 128;
    const int bn   = blockIdx.x * 128;

    const int ar[4] = { (tid + 0) >> 3, (tid + 256) >> 3, (tid + 512) >> 3, (tid + 768) >> 3 };
    const int ac    = (tid & 7) * 4;
    const int br[4] = { (tid + 0) >> 5, (tid + 256) >> 5, (tid + 512) >> 5, (tid + 768) >> 5 };
    const int bc    = (tid & 31) * 4;

    float c[4][4][4] = {};
    const int ntiles = K >> 5;

    {
#pragma unroll
        for (int u = 0; u < 4; u++)
            cp_async16(Asm + ar[u] * AS_STRIDE + ac, A + (size_t)(bm + ar[u]) * K + ac);
#pragma unroll
        for (int u = 0; u < 4; u++)
            cp_async16(Bsm + br[u] * BS_STRIDE + bc, Bm + (size_t)br[u] * N + bn + bc);
        CP_COMMIT();
    }

    for (int t = 0; t < ntiles; t++) {
        CP_WAIT0();
        __syncthreads();

        if (t + 1 < ntiles) {
            const int k0 = (t + 1) << 5;
            float* An = Asm + ((t + 1) & 1) * AS_ELEMS;
            float* Bn = Bsm + ((t + 1) & 1) * BS_ELEMS;
#pragma unroll
            for (int u = 0; u < 4; u++)
                cp_async16(An + ar[u] * AS_STRIDE + ac, A + (size_t)(bm + ar[u]) * K + k0 + ac);
#pragma unroll
            for (int u = 0; u < 4; u++)
                cp_async16(Bn + br[u] * BS_STRIDE + bc, Bm + (size_t)(k0 + br[u]) * N + bn + bc);
            CP_COMMIT();
        }

        const float* Ab = Asm + (t & 1) * AS_ELEMS;
        const float* Bb = Bsm + (t & 1) * BS_ELEMS;
#pragma unroll
        for (int kk = 0; kk < 4; kk++) {
            const int kb = kk * 8;
            uint32_t af[4][4], bf[4][2];
#pragma unroll
            for (int mt = 0; mt < 4; mt++)
                ldsm_x4(af[mt][0], af[mt][1], af[mt][2], af[mt][3],
                        Ab, wm * 64 + mt * 16, kb, AS_STRIDE);
#pragma unroll
            for (int nt = 0; nt < 4; nt++) {
                int cn = wn * 32 + nt * 8 + gid;
                bf[nt][0] = __float_as_uint(Bb[(kb + tig    ) * BS_STRIDE + cn]);
                bf[nt][1] = __float_as_uint(Bb[(kb + tig + 4) * BS_STRIDE + cn]);
            }
#pragma unroll
            for (int mt = 0; mt < 4; mt++)
#pragma unroll
                for (int nt = 0; nt < 4; nt++)
                    asm volatile(
                        "mma.sync.aligned.m16n8k8.row.col.f32.tf32.tf32.f32 "
                        "{%0,%1,%2,%3},{%4,%5,%6,%7},{%8,%9},{%0,%1,%2,%3};"
                        : "+f"(c[mt][nt][0]), "+f"(c[mt][nt][1]),
                          "+f"(c[mt][nt][2]), "+f"(c[mt][nt][3])
                        : "r"(af[mt][0]), "r"(af[mt][1]), "r"(af[mt][2]), "r"(af[mt][3]),
                          "r"(bf[nt][0]), "r"(bf[nt][1]));
        }
    }

#pragma unroll
    for (int mt = 0; mt < 4; mt++) {
        int r0 = bm + wm * 64 + mt * 16 + gid;
#pragma unroll
        for (int nt = 0; nt < 4; nt++) {
            int cn = bn + wn * 32 + nt * 8 + tig * 2;
            if (NGUARD && cn >= n_out) continue;
            float v0 = c[mt][nt][0], v1 = c[mt][nt][1];
            float v2 = c[mt][nt][2], v3 = c[mt][nt][3];
            if (BIAS) {
                float b0 = bias[cn], b1 = bias[cn + 1];
                v0 += b0; v1 += b1; v2 += b0; v3 += b1;
            }
            if (RELU) {
                v0 = fmaxf(v0, 0.f); v1 = fmaxf(v1, 0.f);
                v2 = fmaxf(v2, 0.f); v3 = fmaxf(v3, 0.f);
            }
            if (RESID) {
                const float2 ra = *(const float2*)(resid + (size_t)r0 * ldc + cn);
                const float2 rb = *(const float2*)(resid + (size_t)(r0 + 8) * ldc + cn);
                v0 += ra.x; v1 += ra.y; v2 += rb.x; v3 += rb.y;
            }
            if (ROUND_OUT) {
                v0 = roundtf(v0); v1 = roundtf(v1);
                v2 = roundtf(v2); v3 = roundtf(v3);
            }
            *(float2*)(C + (size_t)r0 * ldc + cn)       = make_float2(v0, v1);
            *(float2*)(C + (size_t)(r0 + 8) * ldc + cn) = make_float2(v2, v3);
        }
    }
}

// ---------------- TF32 mma flash attention (split K/V wait groups) ----------------
#define QS_STR 68
#define KS_STR 68
#define VS_STR 72
#define SS_STR 68
#define FA_SMEM_FLOATS (64*QS_STR + 64*KS_STR + 64*VS_STR + 64*SS_STR + 256 + 256 + 64*3)

__global__ __launch_bounds__(256)
void flash_attn(const float* __restrict__ qkv, float* __restrict__ o) {
    extern __shared__ float sm[];
    float* Qs      = sm;
    float* Ks      = Qs + 64 * QS_STR;
    float* Vs      = Ks + 64 * KS_STR;
    float* Ss      = Vs + 64 * VS_STR;
    float* part_m  = Ss + 64 * SS_STR;
    float* part_s  = part_m + 256;
    float* m_s     = part_s + 256;
    float* l_s     = m_s + 64;
    float* alpha_s = l_s + 64;

    const int qt = blockIdx.x;
    const int h  = blockIdx.y;
    const int b  = blockIdx.z;
    const int tid = threadIdx.x;
    const int wid = tid >> 5, lane = tid & 31;
    const int gid = lane >> 2, tig = lane & 3;
    const int wm  = wid & 3;
    const int wn  = wid >> 2;

    const float* base = qkv + (size_t)b * T_ * NQKV_ + h * QKV3_;

    const int cr = tid >> 4;
    const int cc = (tid & 15) * 4;

#pragma unroll
    for (int u = 0; u < 4; u++) {
        int r = cr + u * 16;
        cp_async16(Qs + r * QS_STR + cc, base + (size_t)(qt * 64 + r) * NQKV_ + cc);
    }
    CP_COMMIT();
    if (tid < 64) { m_s[tid] = -1e30f; l_s[tid] = 0.f; }

    float oacc[4][4] = {};
    const int r0 = wm * 16 + gid;

    for (int kt = 0; kt <= qt; kt++) {
        // K group, then V group (separate commits → V overlaps QK+softmax)
#pragma unroll
        for (int u = 0; u < 4; u++) {
            int r = cr + u * 16;
            cp_async16(Ks + r * KS_STR + cc, base + (size_t)(kt * 64 + r) * NQKV_ + HS_ + cc);
        }
        CP_COMMIT();
#pragma unroll
        for (int u = 0; u < 4; u++) {
            int r = cr + u * 16;
            cp_async16(Vs + r * VS_STR + cc, base + (size_t)(kt * 64 + r) * NQKV_ + 2 * HS_ + cc);
        }
        CP_COMMIT();
        CP_WAIT1();          // Q (first iter) + K complete; V may still be in flight
        __syncthreads();

        // S = Q @ K^T
        float sc[4][4] = {};
#pragma unroll
        for (int kk = 0; kk < 8; kk++) {
            const int kb = kk * 8;
            uint32_t af[4], bf[4][2];
            ldsm_x4(af[0], af[1], af[2], af[3], Qs, wm * 16, kb, QS_STR);
#pragma unroll
            for (int p = 0; p < 2; p++) {
                uint32_t d0, d1, d2, d3;
                ldsm_x4(d0, d1, d2, d3, Ks, wn * 32 + p * 16, kb, KS_STR);
                bf[2 * p][0] = d0; bf[2 * p + 1][0] = d1;
                bf[2 * p][1] = d2; bf[2 * p + 1][1] = d3;
            }
#pragma unroll
            for (int nt = 0; nt < 4; nt++)
                asm volatile(
                    "mma.sync.aligned.m16n8k8.row.col.f32.tf32.tf32.f32 "
                    "{%0,%1,%2,%3},{%4,%5,%6,%7},{%8,%9},{%0,%1,%2,%3};"
                    : "+f"(sc[nt][0]), "+f"(sc[nt][1]), "+f"(sc[nt][2]), "+f"(sc[nt][3])
                    : "r"(af[0]), "r"(af[1]), "r"(af[2]), "r"(af[3]),
                      "r"(bf[nt][0]), "r"(bf[nt][1]));
        }

        const bool diag = (kt == qt);
#pragma unroll
        for (int nt = 0; nt < 4; nt++) {
            int gj = wn * 32 + nt * 8 + tig * 2;
            float v0 = sc[nt][0] * 0.125f;
            float v1 = sc[nt][1] * 0.125f;
            float v2 = sc[nt][2] * 0.125f;
            float v3 = sc[nt][3] * 0.125f;
            if (diag) {
                if (gj     > r0    ) v0 = -1e30f;
                if (gj + 1 > r0    ) v1 = -1e30f;
                if (gj     > r0 + 8) v2 = -1e30f;
                if (gj + 1 > r0 + 8) v3 = -1e30f;
            }
            *(float2*)&Ss[(r0    ) * SS_STR + gj] = make_float2(v0, v1);
            *(float2*)&Ss[(r0 + 8) * SS_STR + gj] = make_float2(v2, v3);
        }
        __syncthreads();

        {
            int row = tid >> 2, seg = tid & 3, cb = seg * 16;
            float4 vv[4];
#pragma unroll
            for (int i = 0; i < 4; i++) vv[i] = *(float4*)&Ss[row * SS_STR + cb + i * 4];
            float mx = -1e30f;
#pragma unroll
            for (int i = 0; i < 4; i++)
                mx = fmaxf(mx, fmaxf(fmaxf(vv[i].x, vv[i].y), fmaxf(vv[i].z, vv[i].w)));
            part_m[tid] = mx;
            __syncwarp();
            float m_old = m_s[row];
            float m_new = fmaxf(fmaxf(part_m[row * 4 + 0], part_m[row * 4 + 1]),
                                fmaxf(part_m[row * 4 + 2], part_m[row * 4 + 3]));
            m_new = fmaxf(m_old, m_new);
            float ps = 0.f;
#pragma unroll
            for (int i = 0; i < 4; i++) {
                float4 pv;
                pv.x = roundtf(__expf(vv[i].x - m_new));
                pv.y = roundtf(__expf(vv[i].y - m_new));
                pv.z = roundtf(__expf(vv[i].z - m_new));
                pv.w = roundtf(__expf(vv[i].w - m_new));
                ps += pv.x; ps += pv.y; ps += pv.z; ps += pv.w;
                *(float4*)&Ss[row * SS_STR + cb + i * 4] = pv;
            }
            part_s[tid] = ps;
            __syncwarp();
            if (seg == 0) {
                float alpha = __expf(m_old - m_new);
                alpha_s[row] = alpha;
                m_s[row] = m_new;
                l_s[row] = l_s[row] * alpha +
                           part_s[row * 4 + 0] + part_s[row * 4 + 1] +
                           part_s[row * 4 + 2] + part_s[row * 4 + 3];
            }
        }
        CP_WAIT0();          // V now required
        __syncthreads();

        // O += P @ V
        {
            float a0 = alpha_s[r0], a1 = alpha_s[r0 + 8];
#pragma unroll
            for (int nt = 0; nt < 4; nt++) {
                oacc[nt][0] *= a0; oacc[nt][1] *= a0;
                oacc[nt][2] *= a1; oacc[nt][3] *= a1;
            }
#pragma unroll
            for (int kk = 0; kk < 8; kk++) {
                const int kb = kk * 8;
                uint32_t af[4], bf[4][2];
                ldsm_x4(af[0], af[1], af[2], af[3], Ss, wm * 16, kb, SS_STR);
#pragma unroll
                for (int nt = 0; nt < 4; nt++) {
                    int cn = wn * 32 + nt * 8 + gid;
                    bf[nt][0] = __float_as_uint(Vs[(kb + tig    ) * VS_STR + cn]);
                    bf[nt][1] = __float_as_uint(Vs[(kb + tig + 4) * VS_STR + cn]);
                }
#pragma unroll
                for (int nt = 0; nt < 4; nt++)
                    asm volatile(
                        "mma.sync.aligned.m16n8k8.row.col.f32.tf32.tf32.f32 "
                        "{%0,%1,%2,%3},{%4,%5,%6,%7},{%8,%9},{%0,%1,%2,%3};"
                        : "+f"(oacc[nt][0]), "+f"(oacc[nt][1]), "+f"(oacc[nt][2]), "+f"(oacc[nt][3])
                        : "r"(af[0]), "r"(af[1]), "r"(af[2]), "r"(af[3]),
                          "r"(bf[nt][0]), "r"(bf[nt][1]));
            }
        }
        __syncthreads();
    }

    {
        float invl0 = 1.0f / l_s[r0];
        float invl1 = 1.0f / l_s[r0 + 8];
        int t0 = qt * 64 + r0;
#pragma unroll
        for (int nt = 0; nt < 4; nt++) {
            int cn = wn * 32 + nt * 8 + tig * 2;
            float* p0 = o + (size_t)(b * T_ + t0) * E_ + h * HS_ + cn;
            float* p1 = o + (size_t)(b * T_ + t0 + 8) * E_ + h * HS_ + cn;
            *(float2*)p0 = make_float2(roundtf(oacc[nt][0] * invl0), roundtf(oacc[nt][1] * invl0));
            *(float2*)p1 = make_float2(roundtf(oacc[nt][2] * invl1), roundtf(oacc[nt][3] * invl1));
        }
    }
}

// ---------------- host orchestration ----------------
extern "C" void kernel_launch(void* const* d_in, const int* in_sizes, int n_in,
                              void* d_out, int out_size) {
    const int*   context = (const int*)  d_in[0];
    const float* tok_emb = (const float*)d_in[1];
    const float* pos_emb = (const float*)d_in[2];
    const float* ln1_g   = (const float*)d_in[3];
    const float* ln1_b   = (const float*)d_in[4];
    const float* w_qkv   = (const float*)d_in[5];
    const float* w_proj  = (const float*)d_in[6];
    const float* b_proj  = (const float*)d_in[7];
    const float* ln2_g   = (const float*)d_in[8];
    const float* ln2_b   = (const float*)d_in[9];
    const float* w1      = (const float*)d_in[10];
    const float* b1      = (const float*)d_in[11];
    const float* w2      = (const float*)d_in[12];
    const float* b2      = (const float*)d_in[13];
    const float* lnf_g   = (const float*)d_in[14];
    const float* lnf_b   = (const float*)d_in[15];
    const float* w_head  = (const float*)d_in[16];
    const float* b_head  = (const float*)d_in[17];
    float* out = (float*)d_out;

    float *x, *xn, *qkv, *obuf, *ff, *wq, *wp, *w1r, *w2r, *whr, *bhr;
    cudaGetSymbolAddress((void**)&x,    g_x);
    cudaGetSymbolAddress((void**)&xn,   g_xn);
    cudaGetSymbolAddress((void**)&qkv,  g_qkv);
    cudaGetSymbolAddress((void**)&obuf, g_obuf);
    cudaGetSymbolAddress((void**)&ff,   g_ff);
    cudaGetSymbolAddress((void**)&wq,   g_wq);
    cudaGetSymbolAddress((void**)&wp,   g_wp);
    cudaGetSymbolAddress((void**)&w1r,  g_w1r);
    cudaGetSymbolAddress((void**)&w2r,  g_w2r);
    cudaGetSymbolAddress((void**)&whr,  g_whr);
    cudaGetSymbolAddress((void**)&bhr,  g_bhr);

    static bool attr_done = false;
    if (!attr_done) {
        cudaFuncSetAttribute(flash_attn, cudaFuncAttributeMaxDynamicSharedMemorySize,
                             FA_SMEM_FLOATS * 4);
        cudaFuncSetAttribute(gemm_tf32<false, false, false, true, false>,
                             cudaFuncAttributeMaxDynamicSharedMemorySize, GEMM_SMEM_BYTES);
        cudaFuncSetAttribute(gemm_tf32<false, true, true, false, false>,
                             cudaFuncAttributeMaxDynamicSharedMemorySize, GEMM_SMEM_BYTES);
        cudaFuncSetAttribute(gemm_tf32<true, false, true, true, false>,
                             cudaFuncAttributeMaxDynamicSharedMemorySize, GEMM_SMEM_BYTES);
        cudaFuncSetAttribute(gemm_tf32<false, false, true, false, true>,
                             cudaFuncAttributeMaxDynamicSharedMemorySize, GEMM_SMEM_BYTES);
        attr_done = true;
    }

    prep_all_kernel<<<(NTOT_ + 255) / 256, 256>>>(
        context, tok_emb, pos_emb, w_qkv, w_proj, w1, w2, w_head, b_head,
        x, wq, wp, w1r, w2r, whr, bhr);

    for (int l = 0; l < L_; l++) {
        ln_kernel<<<BT_ / 8, 256>>>(x, ln1_g + l * E_, ln1_b + l * E_, xn);
        {
            dim3 grid(NQKV_ / 128, BT_ / 128);
            gemm_tf32<false, false, false, true, false><<<grid, 256, GEMM_SMEM_BYTES>>>(
                xn, wq + (size_t)l * E_ * NQKV_, nullptr, nullptr, qkv,
                BT_, NQKV_, E_, NQKV_, NQKV_);
        }
        {
            dim3 grid(T_ / 64, H_, B_);
            flash_attn<<<grid, 256, FA_SMEM_FLOATS * 4>>>(qkv, obuf);
        }
        {
            dim3 grid(E_ / 128, BT_ / 128);
            gemm_tf32<false, true, true, false, false><<<grid, 256, GEMM_SMEM_BYTES>>>(
                obuf, wp + (size_t)l * E_ * E_, b_proj + l * E_, x, x,
                BT_, E_, E_, E_, E_);
        }
        ln_kernel<<<BT_ / 8, 256>>>(x, ln2_g + l * E_, ln2_b + l * E_, xn);
        {
            dim3 grid(FF_ / 128, BT_ / 128);
            gemm_tf32<true, false, true, true, false><<<grid, 256, GEMM_SMEM_BYTES>>>(
                xn, w1r + (size_t)l * E_ * FF_, b1 + l * FF_, nullptr, ff,
                BT_, FF_, E_, FF_, FF_);
        }
        {
            dim3 grid(E_ / 128, BT_ / 128);
            gemm_tf32<false, true, true, false, false><<<grid, 256, GEMM_SMEM_BYTES>>>(
                ff, w2r + (size_t)l * FF_ * E_, b2 + l * E_, x, x,
                BT_, E_, FF_, E_, E_);
        }
    }
    ln_kernel<<<BT_ / 8, 256>>>(x, lnf_g, lnf_b, xn);
    {
        dim3 grid(VPAD_ / 128, BT_ / 128);
        gemm_tf32<false, false, true, false, true><<<grid, 256, GEMM_SMEM_BYTES>>>(
            xn, whr, bhr, nullptr, out, BT_, VPAD_, E_, V_, V_);
    }
}

// round 17
// speedup vs baseline: 1.1227x; 1.0039x over previous
#include <cuda_runtime.h>
#include <cuda_bf16.h>
#include <math.h>
#include <stdint.h>

// Problem constants
#define B_ 128
#define T_ 256
#define E_ 384
#define H_ 6
#define HS_ 64
#define L_ 6
#define V_ 78
#define FF_ 1536
#define QKV3_ 192
#define NQKV_ (H_ * QKV3_)  // 1152
#define BT_ (B_ * T_)       // 32768
#define VPAD_ 128

__device__ __forceinline__ uint32_t f2tf32(float f) {
    uint32_t r;
    asm("cvt.rna.tf32.f32 %0, %1;" : "=r"(r) : "f"(f));
    return r;
}
__device__ __forceinline__ float roundtf(float f) { return __uint_as_float(f2tf32(f)); }

// ldmatrix.x4 fragment load from row-major smem (stride in words, 16B-aligned rows).
__device__ __forceinline__ void ldsm_x4(uint32_t& d0, uint32_t& d1, uint32_t& d2, uint32_t& d3,
                                        const float* smem, int row0, int col0, int stride) {
    int lane = threadIdx.x & 31;
    int m = lane >> 3, r = lane & 7;
    const float* addr = smem + (size_t)(row0 + r + (m & 1) * 8) * stride + col0 + (m >> 1) * 4;
    uint32_t saddr = (uint32_t)__cvta_generic_to_shared(addr);
    asm volatile("ldmatrix.sync.aligned.m8n8.x4.shared.b16 {%0,%1,%2,%3}, [%4];"
                 : "=r"(d0), "=r"(d1), "=r"(d2), "=r"(d3) : "r"(saddr));
}

#define PAIR_BAR(p) asm volatile("bar.sync %0, 64;" :: "r"((p) + 1) : "memory")

// ---------------- device scratch ----------------
__device__ float g_x   [BT_ * E_];
__device__ float g_xn  [BT_ * E_];
__device__ float g_qkv [BT_ * NQKV_];
__device__ float g_obuf[BT_ * E_];
__device__ float g_ff  [BT_ * FF_];
__device__ float g_wq  [L_ * E_ * NQKV_];
__device__ float g_wp  [L_ * E_ * E_];
__device__ float g_w1r [L_ * E_ * FF_];
__device__ float g_w2r [L_ * FF_ * E_];
__device__ float g_whr [E_ * VPAD_];
__device__ float g_bhr [VPAD_];

// ---------------- fused prep ----------------
#define NE_ (BT_ * E_)
#define NQ_ (L_ * H_ * E_ * QKV3_)
#define NP_ (L_ * E_ * E_)
#define N1_ (L_ * E_ * FF_)
#define N2_ (L_ * FF_ * E_)
#define NH_ (E_ * VPAD_)
#define NTOT_ (NE_ + NQ_ + NP_ + N1_ + N2_ + NH_ + VPAD_)

__global__ void prep_all_kernel(const int* __restrict__ ctx,
                                const float* __restrict__ tok,
                                const float* __restrict__ pos,
                                const float* __restrict__ wqkv,
                                const float* __restrict__ wproj,
                                const float* __restrict__ w1,
                                const float* __restrict__ w2,
                                const float* __restrict__ whead,
                                const float* __restrict__ bhead,
                                float* __restrict__ x,
                                float* __restrict__ wq,
                                float* __restrict__ wp,
                                float* __restrict__ w1r,
                                float* __restrict__ w2r,
                                float* __restrict__ whr,
                                float* __restrict__ bhr) {
    int i = blockIdx.x * blockDim.x + threadIdx.x;
    if (i < NE_) {
        int e  = i % E_;
        int bt = i / E_;
        int t  = bt % T_;
        x[i] = tok[ctx[bt] * E_ + e] + pos[t * E_ + e];
        return;
    }
    i -= NE_;
    if (i < NQ_) {
        int f = i % QKV3_;
        int e = (i / QKV3_) % E_;
        int h = (i / (QKV3_ * E_)) % H_;
        int l = i / (QKV3_ * E_ * H_);
        wq[((size_t)l * E_ + e) * NQKV_ + h * QKV3_ + f] = roundtf(wqkv[i]);
        return;
    }
    i -= NQ_;
    if (i < NP_) { wp[i] = roundtf(wproj[i]); return; }
    i -= NP_;
    if (i < N1_) { w1r[i] = roundtf(w1[i]); return; }
    i -= N1_;
    if (i < N2_) { w2r[i] = roundtf(w2[i]); return; }
    i -= N2_;
    if (i < NH_) {
        int col = i % VPAD_, row = i / VPAD_;
        whr[i] = (col < V_) ? roundtf(whead[row * V_ + col]) : 0.f;
        return;
    }
    i -= NH_;
    if (i < VPAD_) bhr[i] = (i < V_) ? bhead[i] : 0.f;
}

// ---------------- layernorm ----------------
__global__ __launch_bounds__(256)
void ln_kernel(const float* __restrict__ x,
               const float* __restrict__ g,
               const float* __restrict__ bta,
               float* __restrict__ y) {
    const int warp = threadIdx.x >> 5, lane = threadIdx.x & 31;
    const int row  = blockIdx.x * 8 + warp;
    const float4* xp = (const float4*)(x + (size_t)row * E_);
    const float4* gp = (const float4*)g;
    const float4* bp = (const float4*)bta;
    float4* yp = (float4*)(y + (size_t)row * E_);

    float4 v[3];
    float s = 0.f, sq = 0.f;
#pragma unroll
    for (int i = 0; i < 3; i++) {
        v[i] = xp[lane + i * 32];
        s  += v[i].x + v[i].y + v[i].z + v[i].w;
        sq += v[i].x * v[i].x + v[i].y * v[i].y + v[i].z * v[i].z + v[i].w * v[i].w;
    }
#pragma unroll
    for (int off = 16; off; off >>= 1) {
        s  += __shfl_xor_sync(0xffffffffu, s,  off);
        sq += __shfl_xor_sync(0xffffffffu, sq, off);
    }
    const float invE = 1.0f / E_;
    float mu  = s * invE;
    float var = sq * invE - mu * mu;
    float inv = rsqrtf(var + 1e-5f);
#pragma unroll
    for (int i = 0; i < 3; i++) {
        float4 gv = gp[lane + i * 32];
        float4 bv = bp[lane + i * 32];
        float4 ov;
        ov.x = roundtf((v[i].x - mu) * inv * gv.x + bv.x);
        ov.y = roundtf((v[i].y - mu) * inv * gv.y + bv.y);
        ov.z = roundtf((v[i].z - mu) * inv * gv.z + bv.z);
        ov.w = roundtf((v[i].w - mu) * inv * gv.w + bv.w);
        yp[lane + i * 32] = ov;
    }
}

// ---------------- cp.async helpers ----------------
__device__ __forceinline__ void cp_async16(float* smem_ptr, const float* gptr) {
    uint32_t saddr = (uint32_t)__cvta_generic_to_shared(smem_ptr);
    asm volatile("cp.async.cg.shared.global [%0], [%1], 16;" :: "r"(saddr), "l"(gptr));
}
#define CP_COMMIT() asm volatile("cp.async.commit_group;")
#define CP_WAIT0()  asm volatile("cp.async.wait_group 0;")

// ---------------- TF32 GEMM (R14: 2-stage cp.async + ldmatrix A-fragments) ----------------
#define AS_STRIDE 36
#define BS_STRIDE 136
#define AS_ELEMS (128 * AS_STRIDE)
#define BS_ELEMS (32 * BS_STRIDE)
#define GEMM_SMEM_BYTES ((2 * AS_ELEMS + 2 * BS_ELEMS) * 4)   // 71680

template <bool RELU, bool RESID, bool BIAS, bool ROUND_OUT, bool NGUARD>
__global__ __launch_bounds__(256, 2)
void gemm_tf32(const float* __restrict__ A, const float* __restrict__ Bm,
               const float* __restrict__ bias, const float* __restrict__ resid,
               float* __restrict__ C, int M, int N, int K, int ldc, int n_out) {
    extern __shared__ float sm[];
    float* Asm = sm;
    float* Bsm = sm + 2 * AS_ELEMS;

    const int tid  = threadIdx.x;
    const int wid  = tid >> 5, lane = tid & 31;
    const int gid  = lane >> 2, tig = lane & 3;
    const int wm   = wid & 1;
    const int wn   = wid >> 1;
    const int bm   = blockIdx.y * 128;
    const int bn   = blockIdx.x * 128;

    const int ar[4] = { (tid + 0) >> 3, (tid + 256) >> 3, (tid + 512) >> 3, (tid + 768) >> 3 };
    const int ac    = (tid & 7) * 4;
    const int br[4] = { (tid + 0) >> 5, (tid + 256) >> 5, (tid + 512) >> 5, (tid + 768) >> 5 };
    const int bc    = (tid & 31) * 4;

    float c[4][4][4] = {};
    const int ntiles = K >> 5;

    {
#pragma unroll
        for (int u = 0; u < 4; u++)
            cp_async16(Asm + ar[u] * AS_STRIDE + ac, A + (size_t)(bm + ar[u]) * K + ac);
#pragma unroll
        for (int u = 0; u < 4; u++)
            cp_async16(Bsm + br[u] * BS_STRIDE + bc, Bm + (size_t)br[u] * N + bn + bc);
        CP_COMMIT();
    }

    for (int t = 0; t < ntiles; t++) {
        CP_WAIT0();
        __syncthreads();

        if (t + 1 < ntiles) {
            const int k0 = (t + 1) << 5;
            float* An = Asm + ((t + 1) & 1) * AS_ELEMS;
            float* Bn = Bsm + ((t + 1) & 1) * BS_ELEMS;
#pragma unroll
            for (int u = 0; u < 4; u++)
                cp_async16(An + ar[u] * AS_STRIDE + ac, A + (size_t)(bm + ar[u]) * K + k0 + ac);
#pragma unroll
            for (int u = 0; u < 4; u++)
                cp_async16(Bn + br[u] * BS_STRIDE + bc, Bm + (size_t)(k0 + br[u]) * N + bn + bc);
            CP_COMMIT();
        }

        const float* Ab = Asm + (t & 1) * AS_ELEMS;
        const float* Bb = Bsm + (t & 1) * BS_ELEMS;
#pragma unroll
        for (int kk = 0; kk < 4; kk++) {
            const int kb = kk * 8;
            uint32_t af[4][4], bf[4][2];
#pragma unroll
            for (int mt = 0; mt < 4; mt++)
                ldsm_x4(af[mt][0], af[mt][1], af[mt][2], af[mt][3],
                        Ab, wm * 64 + mt * 16, kb, AS_STRIDE);
#pragma unroll
            for (int nt = 0; nt < 4; nt++) {
                int cn = wn * 32 + nt * 8 + gid;
                bf[nt][0] = __float_as_uint(Bb[(kb + tig    ) * BS_STRIDE + cn]);
                bf[nt][1] = __float_as_uint(Bb[(kb + tig + 4) * BS_STRIDE + cn]);
            }
#pragma unroll
            for (int mt = 0; mt < 4; mt++)
#pragma unroll
                for (int nt = 0; nt < 4; nt++)
                    asm volatile(
                        "mma.sync.aligned.m16n8k8.row.col.f32.tf32.tf32.f32 "
                        "{%0,%1,%2,%3},{%4,%5,%6,%7},{%8,%9},{%0,%1,%2,%3};"
                        : "+f"(c[mt][nt][0]), "+f"(c[mt][nt][1]),
                          "+f"(c[mt][nt][2]), "+f"(c[mt][nt][3])
                        : "r"(af[mt][0]), "r"(af[mt][1]), "r"(af[mt][2]), "r"(af[mt][3]),
                          "r"(bf[nt][0]), "r"(bf[nt][1]));
        }
    }

#pragma unroll
    for (int mt = 0; mt < 4; mt++) {
        int r0 = bm + wm * 64 + mt * 16 + gid;
#pragma unroll
        for (int nt = 0; nt < 4; nt++) {
            int cn = bn + wn * 32 + nt * 8 + tig * 2;
            if (NGUARD && cn >= n_out) continue;
            float v0 = c[mt][nt][0], v1 = c[mt][nt][1];
            float v2 = c[mt][nt][2], v3 = c[mt][nt][3];
            if (BIAS) {
                float b0 = bias[cn], b1 = bias[cn + 1];
                v0 += b0; v1 += b1; v2 += b0; v3 += b1;
            }
            if (RELU) {
                v0 = fmaxf(v0, 0.f); v1 = fmaxf(v1, 0.f);
                v2 = fmaxf(v2, 0.f); v3 = fmaxf(v3, 0.f);
            }
            if (RESID) {
                const float2 ra = *(const float2*)(resid + (size_t)r0 * ldc + cn);
                const float2 rb = *(const float2*)(resid + (size_t)(r0 + 8) * ldc + cn);
                v0 += ra.x; v1 += ra.y; v2 += rb.x; v3 += rb.y;
            }
            if (ROUND_OUT) {
                v0 = roundtf(v0); v1 = roundtf(v1);
                v2 = roundtf(v2); v3 = roundtf(v3);
            }
            *(float2*)(C + (size_t)r0 * ldc + cn)       = make_float2(v0, v1);
            *(float2*)(C + (size_t)(r0 + 8) * ldc + cn) = make_float2(v2, v3);
        }
    }
}

// ---------------- TF32 mma flash attention (pair-scoped barriers) ----------------
#define QS_STR 68
#define KS_STR 68
#define VS_STR 72
#define SS_STR 68
#define FA_SMEM_FLOATS (64*QS_STR + 64*KS_STR + 64*VS_STR + 64*SS_STR + 256 + 256 + 64*3)

__global__ __launch_bounds__(256)
void flash_attn(const float* __restrict__ qkv, float* __restrict__ o) {
    extern __shared__ float sm[];
    float* Qs      = sm;
    float* Ks      = Qs + 64 * QS_STR;
    float* Vs      = Ks + 64 * KS_STR;
    float* Ss      = Vs + 64 * VS_STR;
    float* part_m  = Ss + 64 * SS_STR;
    float* part_s  = part_m + 256;
    float* m_s     = part_s + 256;
    float* l_s     = m_s + 64;
    float* alpha_s = l_s + 64;

    const int qt = blockIdx.x;
    const int h  = blockIdx.y;
    const int b  = blockIdx.z;
    const int tid = threadIdx.x;
    const int wid = tid >> 5, lane = tid & 31;
    const int gid = lane >> 2, tig = lane & 3;
    const int wm  = wid & 3;      // pair id 0..3
    const int wn  = wid >> 2;     // 0/1 within pair

    const float* base = qkv + (size_t)b * T_ * NQKV_ + h * QKV3_;

    const int cr = tid >> 4;
    const int cc = (tid & 15) * 4;

#pragma unroll
    for (int u = 0; u < 4; u++) {
        int r = cr + u * 16;
        cp_async16(Qs + r * QS_STR + cc, base + (size_t)(qt * 64 + r) * NQKV_ + cc);
    }
    CP_COMMIT();
    if (tid < 64) { m_s[tid] = -1e30f; l_s[tid] = 0.f; }

    float oacc[4][4] = {};
    const int r0 = wm * 16 + gid;

    // pair-local softmax coordinates: 64 threads of pair wm own rows wm*16..+15
    const int plocal = wn * 32 + lane;           // 0..63 within pair
    const int srow   = wm * 16 + (plocal >> 2);  // softmax row for this thread
    const int sseg   = plocal & 3;               // 4 threads per row (same warp)
    const int pslot  = wm * 64 + plocal;         // unique part_m/part_s slot

    for (int kt = 0; kt <= qt; kt++) {
        // K+V tiles, single group
#pragma unroll
        for (int u = 0; u < 4; u++) {
            int r = cr + u * 16;
            const float* rowp = base + (size_t)(kt * 64 + r) * NQKV_;
            cp_async16(Ks + r * KS_STR + cc, rowp + HS_ + cc);
            cp_async16(Vs + r * VS_STR + cc, rowp + 2 * HS_ + cc);
        }
        CP_COMMIT();
        CP_WAIT0();
        __syncthreads();             // full: K/V/Q visibility across block

        // S = Q @ K^T
        float sc[4][4] = {};
#pragma unroll
        for (int kk = 0; kk < 8; kk++) {
            const int kb = kk * 8;
            uint32_t af[4], bf[4][2];
            ldsm_x4(af[0], af[1], af[2], af[3], Qs, wm * 16, kb, QS_STR);
#pragma unroll
            for (int p = 0; p < 2; p++) {
                uint32_t d0, d1, d2, d3;
                ldsm_x4(d0, d1, d2, d3, Ks, wn * 32 + p * 16, kb, KS_STR);
                bf[2 * p][0] = d0; bf[2 * p + 1][0] = d1;
                bf[2 * p][1] = d2; bf[2 * p + 1][1] = d3;
            }
#pragma unroll
            for (int nt = 0; nt < 4; nt++)
                asm volatile(
                    "mma.sync.aligned.m16n8k8.row.col.f32.tf32.tf32.f32 "
                    "{%0,%1,%2,%3},{%4,%5,%6,%7},{%8,%9},{%0,%1,%2,%3};"
                    : "+f"(sc[nt][0]), "+f"(sc[nt][1]), "+f"(sc[nt][2]), "+f"(sc[nt][3])
                    : "r"(af[0]), "r"(af[1]), "r"(af[2]), "r"(af[3]),
                      "r"(bf[nt][0]), "r"(bf[nt][1]));
        }

        const bool diag = (kt == qt);
#pragma unroll
        for (int nt = 0; nt < 4; nt++) {
            int gj = wn * 32 + nt * 8 + tig * 2;
            float v0 = sc[nt][0] * 0.125f;
            float v1 = sc[nt][1] * 0.125f;
            float v2 = sc[nt][2] * 0.125f;
            float v3 = sc[nt][3] * 0.125f;
            if (diag) {
                if (gj     > r0    ) v0 = -1e30f;
                if (gj + 1 > r0    ) v1 = -1e30f;
                if (gj     > r0 + 8) v2 = -1e30f;
                if (gj + 1 > r0 + 8) v3 = -1e30f;
            }
            *(float2*)&Ss[(r0    ) * SS_STR + gj] = make_float2(v0, v1);
            *(float2*)&Ss[(r0 + 8) * SS_STR + gj] = make_float2(v2, v3);
        }
        PAIR_BAR(wm);                // pair: both warps wrote pair rows of Ss

        // softmax on pair rows (4 threads/row, same warp)
        {
            int cb = sseg * 16;
            float4 vv[4];
#pragma unroll
            for (int i = 0; i < 4; i++) vv[i] = *(float4*)&Ss[srow * SS_STR + cb + i * 4];
            float mx = -1e30f;
#pragma unroll
            for (int i = 0; i < 4; i++)
                mx = fmaxf(mx, fmaxf(fmaxf(vv[i].x, vv[i].y), fmaxf(vv[i].z, vv[i].w)));
            part_m[pslot] = mx;
            __syncwarp();
            float m_old = m_s[srow];
            int pb = pslot & ~3;
            float m_new = fmaxf(fmaxf(part_m[pb + 0], part_m[pb + 1]),
                                fmaxf(part_m[pb + 2], part_m[pb + 3]));
            m_new = fmaxf(m_old, m_new);
            float ps = 0.f;
#pragma unroll
            for (int i = 0; i < 4; i++) {
                float4 pv;
                pv.x = roundtf(__expf(vv[i].x - m_new));
                pv.y = roundtf(__expf(vv[i].y - m_new));
                pv.z = roundtf(__expf(vv[i].z - m_new));
                pv.w = roundtf(__expf(vv[i].w - m_new));
                ps += pv.x; ps += pv.y; ps += pv.z; ps += pv.w;
                *(float4*)&Ss[srow * SS_STR + cb + i * 4] = pv;
            }
            part_s[pslot] = ps;
            __syncwarp();
            if (sseg == 0) {
                float alpha = __expf(m_old - m_new);
                alpha_s[srow] = alpha;
                m_s[srow] = m_new;
                l_s[srow] = l_s[srow] * alpha +
                            part_s[pb + 0] + part_s[pb + 1] +
                            part_s[pb + 2] + part_s[pb + 3];
            }
        }
        PAIR_BAR(wm);                // pair: P + alpha ready for pair rows

        // O += P @ V
        {
            float a0 = alpha_s[r0], a1 = alpha_s[r0 + 8];
#pragma unroll
            for (int nt = 0; nt < 4; nt++) {
                oacc[nt][0] *= a0; oacc[nt][1] *= a0;
                oacc[nt][2] *= a1; oacc[nt][3] *= a1;
            }
#pragma unroll
            for (int kk = 0; kk < 8; kk++) {
                const int kb = kk * 8;
                uint32_t af[4], bf[4][2];
                ldsm_x4(af[0], af[1], af[2], af[3], Ss, wm * 16, kb, SS_STR);
#pragma unroll
                for (int nt = 0; nt < 4; nt++) {
                    int cn = wn * 32 + nt * 8 + gid;
                    bf[nt][0] = __float_as_uint(Vs[(kb + tig    ) * VS_STR + cn]);
                    bf[nt][1] = __float_as_uint(Vs[(kb + tig + 4) * VS_STR + cn]);
                }
#pragma unroll
                for (int nt = 0; nt < 4; nt++)
                    asm volatile(
                        "mma.sync.aligned.m16n8k8.row.col.f32.tf32.tf32.f32 "
                        "{%0,%1,%2,%3},{%4,%5,%6,%7},{%8,%9},{%0,%1,%2,%3};"
                        : "+f"(oacc[nt][0]), "+f"(oacc[nt][1]), "+f"(oacc[nt][2]), "+f"(oacc[nt][3])
                        : "r"(af[0]), "r"(af[1]), "r"(af[2]), "r"(af[3]),
                          "r"(bf[nt][0]), "r"(bf[nt][1]));
            }
        }
        __syncthreads();             // full: Ks/Vs safe to overwrite next iter
    }

    {
        float invl0 = 1.0f / l_s[r0];
        float invl1 = 1.0f / l_s[r0 + 8];
        int t0 = qt * 64 + r0;
#pragma unroll
        for (int nt = 0; nt < 4; nt++) {
            int cn = wn * 32 + nt * 8 + tig * 2;
            float* p0 = o + (size_t)(b * T_ + t0) * E_ + h * HS_ + cn;
            float* p1 = o + (size_t)(b * T_ + t0 + 8) * E_ + h * HS_ + cn;
            *(float2*)p0 = make_float2(roundtf(oacc[nt][0] * invl0), roundtf(oacc[nt][1] * invl0));
            *(float2*)p1 = make_float2(roundtf(oacc[nt][2] * invl1), roundtf(oacc[nt][3] * invl1));
        }
    }
}

// ---------------- host orchestration ----------------
extern "C" void kernel_launch(void* const* d_in, const int* in_sizes, int n_in,
                              void* d_out, int out_size) {
    const int*   context = (const int*)  d_in[0];
    const float* tok_emb = (const float*)d_in[1];
    const float* pos_emb = (const float*)d_in[2];
    const float* ln1_g   = (const float*)d_in[3];
    const float* ln1_b   = (const float*)d_in[4];
    const float* w_qkv   = (const float*)d_in[5];
    const float* w_proj  = (const float*)d_in[6];
    const float* b_proj  = (const float*)d_in[7];
    const float* ln2_g   = (const float*)d_in[8];
    const float* ln2_b   = (const float*)d_in[9];
    const float* w1      = (const float*)d_in[10];
    const float* b1      = (const float*)d_in[11];
    const float* w2      = (const float*)d_in[12];
    const float* b2      = (const float*)d_in[13];
    const float* lnf_g   = (const float*)d_in[14];
    const float* lnf_b   = (const float*)d_in[15];
    const float* w_head  = (const float*)d_in[16];
    const float* b_head  = (const float*)d_in[17];
    float* out = (float*)d_out;

    float *x, *xn, *qkv, *obuf, *ff, *wq, *wp, *w1r, *w2r, *whr, *bhr;
    cudaGetSymbolAddress((void**)&x,    g_x);
    cudaGetSymbolAddress((void**)&xn,   g_xn);
    cudaGetSymbolAddress((void**)&qkv,  g_qkv);
    cudaGetSymbolAddress((void**)&obuf, g_obuf);
    cudaGetSymbolAddress((void**)&ff,   g_ff);
    cudaGetSymbolAddress((void**)&wq,   g_wq);
    cudaGetSymbolAddress((void**)&wp,   g_wp);
    cudaGetSymbolAddress((void**)&w1r,  g_w1r);
    cudaGetSymbolAddress((void**)&w2r,  g_w2r);
    cudaGetSymbolAddress((void**)&whr,  g_whr);
    cudaGetSymbolAddress((void**)&bhr,  g_bhr);

    static bool attr_done = false;
    if (!attr_done) {
        cudaFuncSetAttribute(flash_attn, cudaFuncAttributeMaxDynamicSharedMemorySize,
                             FA_SMEM_FLOATS * 4);
        cudaFuncSetAttribute(gemm_tf32<false, false, false, true, false>,
                             cudaFuncAttributeMaxDynamicSharedMemorySize, GEMM_SMEM_BYTES);
        cudaFuncSetAttribute(gemm_tf32<false, true, true, false, false>,
                             cudaFuncAttributeMaxDynamicSharedMemorySize, GEMM_SMEM_BYTES);
        cudaFuncSetAttribute(gemm_tf32<true, false, true, true, false>,
                             cudaFuncAttributeMaxDynamicSharedMemorySize, GEMM_SMEM_BYTES);
        cudaFuncSetAttribute(gemm_tf32<false, false, true, false, true>,
                             cudaFuncAttributeMaxDynamicSharedMemorySize, GEMM_SMEM_BYTES);
        attr_done = true;
    }

    prep_all_kernel<<<(NTOT_ + 255) / 256, 256>>>(
        context, tok_emb, pos_emb, w_qkv, w_proj, w1, w2, w_head, b_head,
        x, wq, wp, w1r, w2r, whr, bhr);

    for (int l = 0; l < L_; l++) {
        ln_kernel<<<BT_ / 8, 256>>>(x, ln1_g + l * E_, ln1_b + l * E_, xn);
        {
            dim3 grid(NQKV_ / 128, BT_ / 128);
            gemm_tf32<false, false, false, true, false><<<grid, 256, GEMM_SMEM_BYTES>>>(
                xn, wq + (size_t)l * E_ * NQKV_, nullptr, nullptr, qkv,
                BT_, NQKV_, E_, NQKV_, NQKV_);
        }
        {
            dim3 grid(T_ / 64, H_, B_);
            flash_attn<<<grid, 256, FA_SMEM_FLOATS * 4>>>(qkv, obuf);
        }
        {
            dim3 grid(E_ / 128, BT_ / 128);
            gemm_tf32<false, true, true, false, false><<<grid, 256, GEMM_SMEM_BYTES>>>(
                obuf, wp + (size_t)l * E_ * E_, b_proj + l * E_, x, x,
                BT_, E_, E_, E_, E_);
        }
        ln_kernel<<<BT_ / 8, 256>>>(x, ln2_g + l * E_, ln2_b + l * E_, xn);
        {
            dim3 grid(FF_ / 128, BT_ / 128);
            gemm_tf32<true, false, true, true, false><<<grid, 256, GEMM_SMEM_BYTES>>>(
                xn, w1r + (size_t)l * E_ * FF_, b1 + l * FF_, nullptr, ff,
                BT_, FF_, E_, FF_, FF_);
        }
        {
            dim3 grid(E_ / 128, BT_ / 128);
            gemm_tf32<false, true, true, false, false><<<grid, 256, GEMM_SMEM_BYTES>>>(
                ff, w2r + (size_t)l * FF_ * E_, b2 + l * E_, x, x,
                BT_, E_, FF_, E_, E_);
        }
    }
    ln_kernel<<<BT_ / 8, 256>>>(x, lnf_g, lnf_b, xn);
    {
        dim3 grid(VPAD_ / 128, BT_ / 128);
        gemm_tf32<false, false, true, false, true><<<grid, 256, GEMM_SMEM_BYTES>>>(
            xn, whr, bhr, nullptr, out, BT_, VPAD_, E_, V_, V_);
    }
}